// round 1
// baseline (speedup 1.0000x reference)
#include <cuda_runtime.h>
#include <cuda_bf16.h>
#include <cstdint>

// Problem constants
#define Bb 2
#define Cc 256
#define Hh 128
#define Ww 128
#define Oo 256
#define HW 16384            // H*W
#define DG 4
#define GC 64               // channels per deform group
#define NTAP 9
#define NGT 36              // DG * NTAP
#define OFFC 72             // DG*9*2 offset channels

// Scratch (device globals: allocation-free rule)
__device__ float g_off[Bb * OFFC * HW];        // offset field [b][72][h][w]
__device__ float g_wt[NGT * GC * Oo];          // weights as [g*9+tap][c][o]

// ---------------------------------------------------------------------------
// K0: transpose deform weights [O][C][3][3] -> [gt][c][o]
// ---------------------------------------------------------------------------
__global__ void k_transpose_w(const float* __restrict__ w) {
    int idx = blockIdx.x * blockDim.x + threadIdx.x;
    if (idx >= Oo * Cc * 9) return;
    int o = idx / (Cc * 9);
    int r = idx % (Cc * 9);
    int gc = r / 9;
    int tap = r % 9;
    int g = gc / GC;
    int c = gc % GC;
    g_wt[((g * 9 + tap) * GC + c) * Oo + o] = w[idx];
}

// ---------------------------------------------------------------------------
// K1: offset field = 1x1 conv (72x256 matvec per pixel) + bias
// block: 128 threads = 128 consecutive pixels (one row segment)
// smem: weights transposed [c][72]  (73728 B, needs dyn-smem attr)
// ---------------------------------------------------------------------------
__global__ __launch_bounds__(128) void k_offset(const float* __restrict__ x,
                                                const float* __restrict__ w_off,
                                                const float* __restrict__ b_off) {
    extern __shared__ float ws[];  // [256][72], c-major
    for (int i = threadIdx.x; i < OFFC * Cc; i += blockDim.x) {
        int o = i / Cc, c = i % Cc;
        ws[c * OFFC + o] = w_off[i];
    }
    __syncthreads();

    int pix = blockIdx.x * 128 + threadIdx.x;   // 0..32767
    int b = pix >> 14;
    int hw = pix & (HW - 1);
    const float* xp = x + (size_t)b * Cc * HW + hw;

    float4 acc[18];
#pragma unroll
    for (int i = 0; i < 18; i++) acc[i] = *(const float4*)&b_off[i * 4];

    for (int c = 0; c < Cc; c++) {
        float v = __ldg(&xp[(size_t)c * HW]);
        const float4* wrow = (const float4*)&ws[c * OFFC];
#pragma unroll
        for (int i = 0; i < 18; i++) {
            float4 w4 = wrow[i];
            acc[i].x = fmaf(v, w4.x, acc[i].x);
            acc[i].y = fmaf(v, w4.y, acc[i].y);
            acc[i].z = fmaf(v, w4.z, acc[i].z);
            acc[i].w = fmaf(v, w4.w, acc[i].w);
        }
    }
    float* op = g_off + (size_t)b * OFFC * HW + hw;
#pragma unroll
    for (int i = 0; i < 18; i++) {
        op[(i * 4 + 0) * HW] = acc[i].x;
        op[(i * 4 + 1) * HW] = acc[i].y;
        op[(i * 4 + 2) * HW] = acc[i].z;
        op[(i * 4 + 3) * HW] = acc[i].w;
    }
}

// ---------------------------------------------------------------------------
// f32x2 packed-FMA helpers (sm_103a FFMA2 via PTX)
// ---------------------------------------------------------------------------
__device__ __forceinline__ unsigned long long pack2(float v) {
    unsigned long long r;
    asm("mov.b64 %0, {%1, %1};" : "=l"(r) : "f"(v));
    return r;
}
__device__ __forceinline__ void fma2(unsigned long long& d, unsigned long long a,
                                     unsigned long long b) {
    asm("fma.rn.f32x2 %0, %1, %2, %0;" : "+l"(d) : "l"(a), "l"(b));
}
__device__ __forceinline__ void unpack2(unsigned long long r, float& lo, float& hi) {
    asm("mov.b64 {%0, %1}, %2;" : "=f"(lo), "=f"(hi) : "l"(r));
}

// ---------------------------------------------------------------------------
// K2: fused deformable conv + ReLU.
// Block = (b, row h, 64-pixel segment) x all 256 output channels.
// For each of 36 (group, tap) iterations:
//   - 64 threads compute bilinear corner weights/indices for the 64 pixels
//   - stage sampled S[64c][64p] (bilinear gathers; x is L2-resident)
//   - stage W-slice [64c][256o] (pre-transposed, coalesced float4 copy)
//   - 8x8 register-tile GEMM accumulate with f32x2 packed FMAs
// smem: sW 64KB + sS 16KB + coords 2KB = 83968 B
// ---------------------------------------------------------------------------
__global__ __launch_bounds__(256, 2) void k_deform(const float* __restrict__ x,
                                                   float* __restrict__ out) {
    extern __shared__ float smem[];
    float* sW = smem;                       // [64][256] c-major rows of o
    float* sS = smem + GC * Oo;             // [64][64]  c-major rows of p
    float* cw = sS + GC * 64;               // [4][64] corner weights
    int* cidx = (int*)(cw + 4 * 64);        // [4][64] clamped y*W+x

    int bx = blockIdx.x;
    int wseg = bx & 1;
    int h = (bx >> 1) & 127;
    int b = bx >> 8;
    int w0 = wseg * 64;
    int tid = threadIdx.x;

    const int to = tid >> 3;      // 0..31 -> o tile
    const int tp = tid & 7;       // 0..7  -> p tile
    const int o0 = to * 8;
    const int p0 = tp * 8;

    // accumulators: 8 o x 4 p-pairs (each pair = packed f32x2 over p,p+1)
    unsigned long long acc2[8][4];
#pragma unroll
    for (int i = 0; i < 8; i++)
#pragma unroll
        for (int j = 0; j < 4; j++) acc2[i][j] = 0ull;

    const int sp = tid & 63;      // staging pixel
    const int cq = tid >> 6;      // staging channel quarter (0..3)

    for (int gt = 0; gt < NGT; ++gt) {
        int g = gt / 9;
        int tap = gt % 9;

        // --- coords for the 64 pixels ---
        if (tid < 64) {
            int p = tid;
            int wp = w0 + p;
            int offbase = (b * OFFC + g * 18 + tap * 2) * HW + h * Ww + wp;
            float dy = g_off[offbase];
            float dx = g_off[offbase + HW];
            float ys = (float)(h - 1 + tap / 3) + dy;
            float xs = (float)(wp - 1 + tap % 3) + dx;
            float y0f = floorf(ys), x0f = floorf(xs);
            float ly = ys - y0f, lx = xs - x0f;
            int y0 = (int)y0f, x0 = (int)x0f;
#pragma unroll
            for (int j = 0; j < 4; j++) {
                int yj = y0 + (j >> 1);
                int xj = x0 + (j & 1);
                float wj = ((j >> 1) ? ly : 1.f - ly) * ((j & 1) ? lx : 1.f - lx);
                bool v = (yj >= 0) && (yj < Hh) && (xj >= 0) && (xj < Ww);
                int yc = min(max(yj, 0), Hh - 1);
                int xc = min(max(xj, 0), Ww - 1);
                cw[j * 64 + p] = v ? wj : 0.f;
                cidx[j * 64 + p] = yc * Ww + xc;
            }
        }
        __syncthreads();

        // --- stage W slice: contiguous 64KB copy (pre-transposed) ---
        {
            const float4* wsrc = (const float4*)(g_wt + (size_t)gt * GC * Oo);
            float4* wdst = (float4*)sW;
#pragma unroll 4
            for (int i = tid; i < GC * Oo / 4; i += 256) wdst[i] = wsrc[i];
        }

        // --- stage sampled S[c][p] via bilinear gathers ---
        {
            float w00 = cw[sp], w01 = cw[64 + sp], w10 = cw[128 + sp], w11 = cw[192 + sp];
            int i00 = cidx[sp], i01 = cidx[64 + sp], i10 = cidx[128 + sp], i11 = cidx[192 + sp];
            const float* xb = x + (size_t)(b * Cc + g * GC + cq * 16) * HW;
#pragma unroll 4
            for (int cc = 0; cc < 16; ++cc) {
                const float* xc = xb + (size_t)cc * HW;
                float v = w00 * __ldg(xc + i00) + w01 * __ldg(xc + i01) +
                          w10 * __ldg(xc + i10) + w11 * __ldg(xc + i11);
                sS[(cq * 16 + cc) * 64 + sp] = v;
            }
        }
        __syncthreads();

        // --- GEMM accumulate: acc[o0..o0+7][p0..p0+7] += W^T * S over 64 c ---
#pragma unroll 4
        for (int k = 0; k < GC; ++k) {
            float4 a0 = *(const float4*)&sW[k * Oo + o0];
            float4 a1 = *(const float4*)&sW[k * Oo + o0 + 4];
            ulonglong2 bA = *(const ulonglong2*)&sS[k * 64 + p0];
            ulonglong2 bB = *(const ulonglong2*)&sS[k * 64 + p0 + 4];
            float av[8] = {a0.x, a0.y, a0.z, a0.w, a1.x, a1.y, a1.z, a1.w};
#pragma unroll
            for (int oi = 0; oi < 8; oi++) {
                unsigned long long ap = pack2(av[oi]);
                fma2(acc2[oi][0], ap, bA.x);
                fma2(acc2[oi][1], ap, bA.y);
                fma2(acc2[oi][2], ap, bB.x);
                fma2(acc2[oi][3], ap, bB.y);
            }
        }
        __syncthreads();
    }

    // --- epilogue: ReLU + store (float4, coalesced within o-rows) ---
    size_t obase = (size_t)b * Oo * HW + h * Ww + w0;
#pragma unroll
    for (int oi = 0; oi < 8; oi++) {
        float r[8];
#pragma unroll
        for (int j = 0; j < 4; j++) {
            float lo, hi;
            unpack2(acc2[oi][j], lo, hi);
            r[2 * j] = fmaxf(lo, 0.f);
            r[2 * j + 1] = fmaxf(hi, 0.f);
        }
        float* dst = out + obase + (size_t)(o0 + oi) * HW + p0;
        *(float4*)dst = make_float4(r[0], r[1], r[2], r[3]);
        *(float4*)(dst + 4) = make_float4(r[4], r[5], r[6], r[7]);
    }
}

// ---------------------------------------------------------------------------
extern "C" void kernel_launch(void* const* d_in, const int* in_sizes, int n_in,
                              void* d_out, int out_size) {
    const float* x = (const float*)d_in[0];        // [2,256,128,128]
    const float* w_off = (const float*)d_in[1];    // [72,256,1,1]
    const float* b_off = (const float*)d_in[2];    // [72]
    const float* w_def = (const float*)d_in[3];    // [256,256,3,3]
    float* out = (float*)d_out;

    const int OFF_SMEM = OFFC * Cc * sizeof(float);                 // 73728
    const int DEF_SMEM = (GC * Oo + GC * 64 + 4 * 64 * 2) * 4;      // 83968

    cudaFuncSetAttribute(k_offset, cudaFuncAttributeMaxDynamicSharedMemorySize, OFF_SMEM);
    cudaFuncSetAttribute(k_deform, cudaFuncAttributeMaxDynamicSharedMemorySize, DEF_SMEM);

    k_transpose_w<<<(Oo * Cc * 9 + 255) / 256, 256>>>(w_def);
    k_offset<<<(Bb * HW) / 128, 128, OFF_SMEM>>>(x, w_off, b_off);
    k_deform<<<Bb * Hh * 2, 256, DEF_SMEM>>>(x, out);
}

// round 3
// speedup vs baseline: 2.3072x; 2.3072x over previous
#include <cuda_runtime.h>
#include <cuda_bf16.h>
#include <cstdint>

// Problem constants
#define Bb 2
#define Cc 256
#define Hh 128
#define Ww 128
#define Oo 256
#define HW 16384            // H*W
#define DG 4
#define GC 64               // channels per deform group
#define OFFC 72             // DG*9*2 offset channels
#define NGT 36              // DG * 9 taps; K-chunk = 64 channels

#define SSTR 68             // padded smem row stride (floats)

// Scratch (device globals: allocation-free rule)
__device__ float g_off[Bb * OFFC * HW];       // offset field [b][72][h][w]
__device__ float g_wt[NGT * Oo * GC];         // weights tf32, [chunk][o][c]

// ---------------------------------------------------------------------------
// helpers
// ---------------------------------------------------------------------------
__device__ __forceinline__ uint32_t smem_u32(const void* p) {
    uint32_t a;
    asm("{ .reg .u64 t; cvta.to.shared.u64 t, %1; cvt.u32.u64 %0, t; }" : "=r"(a) : "l"(p));
    return a;
}
__device__ __forceinline__ float to_tf32(float f) {
    uint32_t u;
    asm("cvt.rna.tf32.f32 %0, %1;" : "=r"(u) : "f"(f));
    return __uint_as_float(u);
}
__device__ __forceinline__ void ldsm4(uint32_t* r, uint32_t addr) {
    asm volatile("ldmatrix.sync.aligned.m8n8.x4.shared.b16 {%0,%1,%2,%3}, [%4];"
                 : "=r"(r[0]), "=r"(r[1]), "=r"(r[2]), "=r"(r[3]) : "r"(addr));
}
__device__ __forceinline__ void mma_tf32(float* c, const uint32_t* a, const uint32_t* b) {
    asm volatile(
        "mma.sync.aligned.m16n8k8.row.col.f32.tf32.tf32.f32 "
        "{%0,%1,%2,%3},{%4,%5,%6,%7},{%8,%9},{%0,%1,%2,%3};"
        : "+f"(c[0]), "+f"(c[1]), "+f"(c[2]), "+f"(c[3])
        : "r"(a[0]), "r"(a[1]), "r"(a[2]), "r"(a[3]), "r"(b[0]), "r"(b[1]));
}
__device__ __forceinline__ void sts128(uint32_t a, float x, float y, float z, float w) {
    asm volatile("st.shared.v4.f32 [%0], {%1,%2,%3,%4};" :: "r"(a), "f"(x), "f"(y), "f"(z), "f"(w));
}

// ---------------------------------------------------------------------------
// K0: transpose deform weights [O][C][3][3] -> [chunk=g*9+tap][o][c(64)] (tf32)
// ---------------------------------------------------------------------------
__global__ void k_transpose_w(const float* __restrict__ w) {
    int idx = blockIdx.x * blockDim.x + threadIdx.x;
    if (idx >= Oo * Cc * 9) return;
    int o = idx / (Cc * 9);
    int r = idx % (Cc * 9);
    int c = r / 9;
    int tap = r % 9;
    int g = c >> 6;
    int cc = c & 63;
    g_wt[((g * 9 + tap) * Oo + o) * GC + cc] = to_tf32(w[idx]);
}

// ---------------------------------------------------------------------------
// K1: offset field = 1x1 conv (72x256 matvec per pixel) + bias
// ---------------------------------------------------------------------------
__global__ __launch_bounds__(128) void k_offset(const float* __restrict__ x,
                                                const float* __restrict__ w_off,
                                                const float* __restrict__ b_off) {
    extern __shared__ float ws[];  // [256][72], c-major
    for (int i = threadIdx.x; i < OFFC * Cc; i += blockDim.x) {
        int o = i / Cc, c = i % Cc;
        ws[c * OFFC + o] = w_off[i];
    }
    __syncthreads();

    int pix = blockIdx.x * 128 + threadIdx.x;
    int b = pix >> 14;
    int hw = pix & (HW - 1);
    const float* xp = x + (size_t)b * Cc * HW + hw;

    float4 acc[18];
#pragma unroll
    for (int i = 0; i < 18; i++) acc[i] = *(const float4*)&b_off[i * 4];

    for (int c = 0; c < Cc; c++) {
        float v = __ldg(&xp[(size_t)c * HW]);
        const float4* wrow = (const float4*)&ws[c * OFFC];
#pragma unroll
        for (int i = 0; i < 18; i++) {
            float4 w4 = wrow[i];
            acc[i].x = fmaf(v, w4.x, acc[i].x);
            acc[i].y = fmaf(v, w4.y, acc[i].y);
            acc[i].z = fmaf(v, w4.z, acc[i].z);
            acc[i].w = fmaf(v, w4.w, acc[i].w);
        }
    }
    float* op = g_off + (size_t)b * OFFC * HW + hw;
#pragma unroll
    for (int i = 0; i < 18; i++) {
        op[(i * 4 + 0) * HW] = acc[i].x;
        op[(i * 4 + 1) * HW] = acc[i].y;
        op[(i * 4 + 2) * HW] = acc[i].z;
        op[(i * 4 + 3) * HW] = acc[i].w;
    }
}

// ---------------------------------------------------------------------------
// K2: fused deformable conv + ReLU, tf32 mma.sync.m16n8k8 (legacy HMMA path).
// CTA tile: 64 pixels (one row segment) x 256 outputs; 36 K-chunks of 64c.
// smem: W [256o][68] 69.6KB + S [64p][68] 17.4KB + coords 2KB.
// Warp w: o in [w*32, w*32+32), all 64 p -> 4 m-tiles x 4 n-tiles, K by 8.
// ---------------------------------------------------------------------------
__global__ __launch_bounds__(256, 2) void k_deform(const float* __restrict__ x,
                                                   float* __restrict__ out) {
    extern __shared__ float dsm[];
    float* sW = dsm;                         // [256][SSTR]
    float* sS = dsm + Oo * SSTR;             // [64][SSTR]
    float* cw = sS + 64 * SSTR;              // [4][64] corner weights
    int* cidx = (int*)(cw + 4 * 64);         // [4][64] clamped y*W+x

    const int bx = blockIdx.x;
    const int wseg = bx & 1;
    const int h = (bx >> 1) & 127;
    const int b = bx >> 8;
    const int w0 = wseg * 64;
    const int tid = threadIdx.x;
    const int wid = tid >> 5;
    const int lid = tid & 31;

    const uint32_t sWb = smem_u32(sW);
    const uint32_t sSb = smem_u32(sS);

    // ldmatrix lane addresses (bytes), before mi/ni/k offsets
    const uint32_t a_row8 = (lid & 7) + ((lid >> 3) & 1) * 8;   // 0..15
    const uint32_t a_col = (lid >> 4) * 4;                      // 0 or 4
    const uint32_t aAddr0 = sSb + (a_row8 * SSTR + a_col) * 4;
    const uint32_t b_row = (lid & 7) + ((lid >> 4) & 1) * 8;    // 0..15
    const uint32_t b_col = ((lid >> 3) & 1) * 4;                // 0 or 4
    const uint32_t bAddr0 = sWb + ((wid * 32 + b_row) * SSTR + b_col) * 4;

    float acc[4][4][4];
#pragma unroll
    for (int i = 0; i < 4; i++)
#pragma unroll
        for (int j = 0; j < 4; j++)
#pragma unroll
            for (int k = 0; k < 4; k++) acc[i][j][k] = 0.f;

    const int sp = tid & 63;      // staging pixel
    const int cq = tid >> 6;      // staging channel quarter (16 c each)

    for (int gt = 0; gt < NGT; ++gt) {
        const int g = gt / 9;
        const int tap = gt - g * 9;

        // --- bilinear coords for the 64 pixels ---
        if (tid < 64) {
            int p = tid;
            int wp = w0 + p;
            const float* offp = g_off + ((size_t)(b * OFFC + g * 18 + tap * 2)) * HW + h * Ww + wp;
            float dy = offp[0];
            float dx = offp[HW];
            float ys = (float)(h - 1 + tap / 3) + dy;
            float xs = (float)(wp - 1 + tap % 3) + dx;
            float y0f = floorf(ys), x0f = floorf(xs);
            float ly = ys - y0f, lx = xs - x0f;
            int y0 = (int)y0f, x0i = (int)x0f;
#pragma unroll
            for (int j = 0; j < 4; j++) {
                int yj = y0 + (j >> 1);
                int xj = x0i + (j & 1);
                float wj = ((j >> 1) ? ly : 1.f - ly) * ((j & 1) ? lx : 1.f - lx);
                bool v = (yj >= 0) && (yj < Hh) && (xj >= 0) && (xj < Ww);
                int yc = min(max(yj, 0), Hh - 1);
                int xc = min(max(xj, 0), Ww - 1);
                cw[j * 64 + p] = v ? wj : 0.f;
                cidx[j * 64 + p] = yc * Ww + xc;
            }
        }
        __syncthreads();

        // --- stage W chunk [256o][64c] -> padded smem ---
        {
            const float4* wsrc = (const float4*)(g_wt + (size_t)gt * Oo * GC);
#pragma unroll
            for (int it = 0; it < 16; ++it) {
                int i = tid + it * 256;       // f4 index, 4096 total
                int o = i >> 4;
                int c4 = i & 15;
                float4 wv = __ldg(&wsrc[i]);
                sts128(sWb + (uint32_t)(o * SSTR + c4 * 4) * 4u, wv.x, wv.y, wv.z, wv.w);
            }
        }

        // --- stage S: sample 16 channels for pixel sp -> [p][c] tf32 ---
        {
            float wt0 = cw[sp], wt1 = cw[64 + sp], wt2 = cw[128 + sp], wt3 = cw[192 + sp];
            int i0 = cidx[sp], i1 = cidx[64 + sp], i2 = cidx[128 + sp], i3 = cidx[192 + sp];
            const float* xb = x + ((size_t)(b * Cc + g * GC + cq * 16)) * HW;
#pragma unroll
            for (int j4 = 0; j4 < 4; ++j4) {
                float v[4];
#pragma unroll
                for (int j = 0; j < 4; ++j) {
                    const float* xc = xb + (size_t)(j4 * 4 + j) * HW;
                    v[j] = to_tf32(wt0 * __ldg(xc + i0) + wt1 * __ldg(xc + i1) +
                                   wt2 * __ldg(xc + i2) + wt3 * __ldg(xc + i3));
                }
                sts128(sSb + (uint32_t)(sp * SSTR + cq * 16 + j4 * 4) * 4u, v[0], v[1], v[2], v[3]);
            }
        }
        __syncthreads();

        // --- GEMM: acc[64p x 32o per warp] += S * W^T over 64 c ---
#pragma unroll
        for (int ks = 0; ks < 8; ++ks) {
            uint32_t afr[4][4];
#pragma unroll
            for (int mi = 0; mi < 4; ++mi)
                ldsm4(afr[mi], aAddr0 + (uint32_t)(mi * 16 * SSTR + ks * 8) * 4u);
            uint32_t bfr[2][4];
#pragma unroll
            for (int pi = 0; pi < 2; ++pi)
                ldsm4(bfr[pi], bAddr0 + (uint32_t)(pi * 16 * SSTR + ks * 8) * 4u);
#pragma unroll
            for (int mi = 0; mi < 4; ++mi)
#pragma unroll
                for (int ni = 0; ni < 4; ++ni)
                    mma_tf32(acc[mi][ni], afr[mi], &bfr[ni >> 1][(ni & 1) * 2]);
        }
        __syncthreads();
    }

    // --- epilogue: ReLU + store ---
    {
        const int gq = lid >> 2;   // 0..7
        const int tq = lid & 3;    // 0..3
#pragma unroll
        for (int mi = 0; mi < 4; ++mi) {
#pragma unroll
            for (int ni = 0; ni < 4; ++ni) {
                int o = wid * 32 + ni * 8 + 2 * tq;
                int p = mi * 16 + gq;
                float* op = out + ((size_t)(b * Oo + o)) * HW + h * Ww + w0 + p;
                op[0] = fmaxf(acc[mi][ni][0], 0.f);
                op[HW] = fmaxf(acc[mi][ni][1], 0.f);
                op[8] = fmaxf(acc[mi][ni][2], 0.f);
                op[HW + 8] = fmaxf(acc[mi][ni][3], 0.f);
            }
        }
    }
}

// ---------------------------------------------------------------------------
extern "C" void kernel_launch(void* const* d_in, const int* in_sizes, int n_in,
                              void* d_out, int out_size) {
    const float* x = (const float*)d_in[0];        // [2,256,128,128]
    const float* w_off = (const float*)d_in[1];    // [72,256,1,1]
    const float* b_off = (const float*)d_in[2];    // [72]
    const float* w_def = (const float*)d_in[3];    // [256,256,3,3]
    float* out = (float*)d_out;

    const int OFF_SMEM = OFFC * Cc * sizeof(float);                     // 73728
    const int DEF_SMEM = (Oo * SSTR + 64 * SSTR + 4 * 64 * 2) * 4;      // 89088

    cudaFuncSetAttribute(k_offset, cudaFuncAttributeMaxDynamicSharedMemorySize, OFF_SMEM);
    cudaFuncSetAttribute(k_deform, cudaFuncAttributeMaxDynamicSharedMemorySize, DEF_SMEM);

    k_transpose_w<<<(Oo * Cc * 9 + 255) / 256, 256>>>(w_def);
    k_offset<<<(Bb * HW) / 128, 128, OFF_SMEM>>>(x, w_off, b_off);
    k_deform<<<Bb * Hh * 2, 256, DEF_SMEM>>>(x, out);
}